// round 16
// baseline (speedup 1.0000x reference)
#include <cuda_runtime.h>
#include <cuda_bf16.h>
#include <cstdint>
#include <cstddef>

// Problem constants
#define BB   4
#define CC   256
#define CQK  32
#define NN   4096          // H*W = 64*64
#define OUT_ELEMS (BB*CC*NN)
#define NSPLIT 8           // n-dim split for stats/write passes

#define LOG2E 1.4426950408889634f

// ---------------- scratch (device globals: allocation-free) ----------------
__device__ __align__(128) float g_q[BB*CQK*NN];    // [b][c][n]
__device__ __align__(128) float g_k[BB*CQK*NN];    // [b][c][n], pre-scaled log2e
__device__ __align__(128) float g_qt[BB*NN*CQK];   // [b][n][c]   (for TC stats)
__device__ __align__(128) float g_kt[BB*NN*CQK];   // [b][m][c], pre-scaled log2e
__device__ __align__(128) __nv_bfloat16 g_vh[BB*CC*NN];   // V bf16
__device__ __align__(128) __nv_bfloat16 g_ah[BB*NN*NN];   // NORMALIZED attn map bf16
__device__ float g_sm[BB*NN];            // inv column sums
__device__ float g_psm[BB*NSPLIT*NN];    // partial column sums

// ---------------- f32x2 packed helpers ----------------
__device__ __forceinline__ unsigned long long f2u_dup(float x) {
    unsigned long long r;
    asm("mov.b64 %0, {%1, %1};" : "=l"(r) : "f"(x));
    return r;
}
__device__ __forceinline__ float2 u2f(unsigned long long v) {
    float2 r;
    asm("mov.b64 {%0, %1}, %2;" : "=f"(r.x), "=f"(r.y) : "l"(v));
    return r;
}
__device__ __forceinline__ unsigned long long fma2(unsigned long long a,
                                                   unsigned long long b,
                                                   unsigned long long c) {
    unsigned long long d;
    asm("fma.rn.f32x2 %0, %1, %2, %3;" : "=l"(d) : "l"(a), "l"(b), "l"(c));
    return d;
}
__device__ __forceinline__ float ex2(float x) {
    float r;
    asm("ex2.approx.ftz.f32 %0, %1;" : "=f"(r) : "f"(x));
    return r;
}
__device__ __forceinline__ uint32_t to_tf32(float x) {
    uint32_t r;
    asm("cvt.rna.tf32.f32 %0, %1;" : "=r"(r) : "f"(x));
    return r;
}
// Markidis split: x = hi + lo in tf32 pieces (error ~2^-22)
__device__ __forceinline__ void split_tf32(float x, uint32_t& hi, uint32_t& lo) {
    hi = to_tf32(x);
    lo = to_tf32(x - __uint_as_float(hi));
}

// ---------------- smem / cp.async helpers ----------------
__device__ __forceinline__ uint32_t smem_u32(const void* p) {
    uint32_t a;
    asm("{ .reg .u64 t; cvta.to.shared.u64 t, %1; cvt.u32.u64 %0, t; }" : "=r"(a) : "l"(p));
    return a;
}
__device__ __forceinline__ void cp16(uint32_t dst, const void* src) {
    asm volatile("cp.async.cg.shared.global [%0], [%1], 16;" :: "r"(dst), "l"(src) : "memory");
}

// =====================================================================
// Kernel 1: q/k projection (f32x2). Writes BOTH [c][n] (for write pass)
// and transposed [n][c] (for TC stats pass). K pre-scaled by log2(e).
// grid (NN/256, B, 2[q|k]), block 128.
// =====================================================================
__global__ __launch_bounds__(128)
void proj_qk_kernel(const float* __restrict__ x,
                    const float* __restrict__ wq, const float* __restrict__ bq,
                    const float* __restrict__ wk, const float* __restrict__ bk)
{
    __shared__ float ws[256*40];
    __shared__ float bs[CQK];

    const int sel = blockIdx.z;
    const float* W  = sel ? wk : wq;
    const float* Bv = sel ? bk : bq;
    float* Out      = sel ? g_k  : g_q;
    float* OutT     = sel ? g_kt : g_qt;
    const float osc = sel ? LOG2E : 1.0f;

    const int t = threadIdx.x;
    for (int idx = t; idx < CQK*CC; idx += 128) {
        int o = idx >> 8;
        int c = idx & 255;
        ws[c*40 + o] = W[idx];
    }
    if (t < CQK) bs[t] = Bv[t];
    __syncthreads();

    const int b = blockIdx.y;
    const int n = blockIdx.x * 256 + t*2;

    unsigned long long acc2[2][16];
#pragma unroll
    for (int i = 0; i < 2; i++)
#pragma unroll
        for (int op = 0; op < 16; op++) acc2[i][op] = 0ull;

    const float* xp = x + (size_t)b*CC*NN + n;
#pragma unroll 2
    for (int c = 0; c < CC; c++) {
        float2 xv = *reinterpret_cast<const float2*>(xp + (size_t)c*NN);
        unsigned long long xd0 = f2u_dup(xv.x);
        unsigned long long xd1 = f2u_dup(xv.y);
        const float* wr = &ws[c*40];
#pragma unroll
        for (int op = 0; op < 16; op++) {
            unsigned long long w2 = *reinterpret_cast<const unsigned long long*>(&wr[op*2]);
            acc2[0][op] = fma2(w2, xd0, acc2[0][op]);
            acc2[1][op] = fma2(w2, xd1, acc2[1][op]);
        }
    }
    float* opt  = Out  + (size_t)b*CQK*NN + n;
    float* optT = OutT + ((size_t)b*NN + n)*CQK;
#pragma unroll
    for (int op = 0; op < 16; op++) {
        float2 p0 = u2f(acc2[0][op]);
        float2 p1 = u2f(acc2[1][op]);
        float v00 = (p0.x + bs[2*op])*osc;       // (o=2op,   n)
        float v10 = (p0.y + bs[2*op + 1])*osc;   // (o=2op+1, n)
        float v01 = (p1.x + bs[2*op])*osc;       // (o=2op,   n+1)
        float v11 = (p1.y + bs[2*op + 1])*osc;
        float2 r0; r0.x = v00; r0.y = v01;
        float2 r1; r1.x = v10; r1.y = v11;
        *reinterpret_cast<float2*>(opt + (size_t)(2*op)*NN)     = r0;
        *reinterpret_cast<float2*>(opt + (size_t)(2*op + 1)*NN) = r1;
        float2 c0; c0.x = v00; c0.y = v10;
        float2 c1; c1.x = v01; c1.y = v11;
        *reinterpret_cast<float2*>(optT + 2*op)        = c0;
        *reinterpret_cast<float2*>(optT + CQK + 2*op)  = c1;
    }
}

// =====================================================================
// Kernel 2: v projection -> bf16 (f32x2). grid (NN/256, 8, B), block 128.
// =====================================================================
__global__ __launch_bounds__(128)
void proj_v_kernel(const float* __restrict__ x,
                   const float* __restrict__ wv, const float* __restrict__ bv)
{
    __shared__ float ws[256*40];
    __shared__ float bs[32];

    const int t  = threadIdx.x;
    const int o0 = blockIdx.y * 32;

    for (int idx = t; idx < 32*CC; idx += 128) {
        int o = idx >> 8;
        int c = idx & 255;
        ws[c*40 + o] = wv[(size_t)(o0 + o)*CC + c];
    }
    if (t < 32) bs[t] = bv[o0 + t];
    __syncthreads();

    const int b = blockIdx.z;
    const int n = blockIdx.x * 256 + t*2;

    unsigned long long acc2[2][16];
#pragma unroll
    for (int i = 0; i < 2; i++)
#pragma unroll
        for (int op = 0; op < 16; op++) acc2[i][op] = 0ull;

    const float* xp = x + (size_t)b*CC*NN + n;
#pragma unroll 2
    for (int c = 0; c < CC; c++) {
        float2 xv = *reinterpret_cast<const float2*>(xp + (size_t)c*NN);
        unsigned long long xd0 = f2u_dup(xv.x);
        unsigned long long xd1 = f2u_dup(xv.y);
        const float* wr = &ws[c*40];
#pragma unroll
        for (int op = 0; op < 16; op++) {
            unsigned long long w2 = *reinterpret_cast<const unsigned long long*>(&wr[op*2]);
            acc2[0][op] = fma2(w2, xd0, acc2[0][op]);
            acc2[1][op] = fma2(w2, xd1, acc2[1][op]);
        }
    }
    __nv_bfloat16* opt = g_vh + (size_t)b*CC*NN + (size_t)o0*NN + n;
#pragma unroll
    for (int op = 0; op < 16; op++) {
        float2 p0 = u2f(acc2[0][op]);
        float2 p1 = u2f(acc2[1][op]);
        __nv_bfloat162 h0, h1;
        h0.x = __float2bfloat16_rn(p0.x + bs[2*op]);
        h0.y = __float2bfloat16_rn(p1.x + bs[2*op]);
        h1.x = __float2bfloat16_rn(p0.y + bs[2*op + 1]);
        h1.y = __float2bfloat16_rn(p1.y + bs[2*op + 1]);
        *reinterpret_cast<__nv_bfloat162*>(opt + (size_t)(2*op)*NN)     = h0;
        *reinterpret_cast<__nv_bfloat162*>(opt + (size_t)(2*op + 1)*NN) = h1;
    }
}

// =====================================================================
// Stats pass (tensor-core): column sums of exp(energy) via SPLIT-tf32
// mma (Markidis: hi*hi + hi*lo + lo*hi -> fp32-grade accuracy).
// energy[m,n] (log2 domain) = sum_c kt[m][c]*qt[n][c]  (NT, K=32).
// grid (NN/64 m-tiles, NSPLIT, B), block 256 (8 warps: 4 m-frags x 2 n-halves).
// =====================================================================
__global__ __launch_bounds__(256)
void attn_stats_tc_kernel()
{
    __shared__ float Kt[64][36];   // [m][c]
    __shared__ float Qt[64][36];   // [n][c]
    __shared__ float red[64][9];

    const int b  = blockIdx.z;
    const int z  = blockIdx.y;
    const int m0 = blockIdx.x * 64;
    const int t  = threadIdx.x;
    const int w  = t >> 5;
    const int lane = t & 31;
    const int lr = lane >> 2;      // 0..7
    const int lc = lane & 3;       // 0..3
    const int wm = w & 3;          // m-group (16 rows)
    const int wn = w >> 2;         // n-half (32 cols)

    // load Kt tile: 64 rows x 32 c = 512 float4, 2 per thread
#pragma unroll
    for (int it = 0; it < 2; it++) {
        int u = t + it*256;        // 0..511
        int row = u >> 3;          // 0..63
        int q4  = u & 7;           // 0..7
        float4 v = *reinterpret_cast<const float4*>(
            &g_kt[((size_t)b*NN + m0 + row)*CQK + q4*4]);
        Kt[row][q4*4+0] = v.x; Kt[row][q4*4+1] = v.y;
        Kt[row][q4*4+2] = v.z; Kt[row][q4*4+3] = v.w;
    }

    float s0 = 0.f, s1 = 0.f;   // sums for m-rows 16wm+lr, 16wm+lr+8

    for (int ch = 0; ch < (NN/NSPLIT)/64; ch++) {
        const int n0 = z*(NN/NSPLIT) + ch*64;
        __syncthreads();
#pragma unroll
        for (int it = 0; it < 2; it++) {
            int u = t + it*256;
            int row = u >> 3;
            int q4  = u & 7;
            float4 v = *reinterpret_cast<const float4*>(
                &g_qt[((size_t)b*NN + n0 + row)*CQK + q4*4]);
            Qt[row][q4*4+0] = v.x; Qt[row][q4*4+1] = v.y;
            Qt[row][q4*4+2] = v.z; Qt[row][q4*4+3] = v.w;
        }
        __syncthreads();

        float acc[4][4];
#pragma unroll
        for (int ni = 0; ni < 4; ni++)
#pragma unroll
            for (int r = 0; r < 4; r++) acc[ni][r] = 0.f;

#pragma unroll
        for (int ks = 0; ks < 4; ks++) {
            const int k0 = ks*8;
            uint32_t ah[4], al[4];
            split_tf32(Kt[16*wm + lr    ][k0 + lc],     ah[0], al[0]);
            split_tf32(Kt[16*wm + lr + 8][k0 + lc],     ah[1], al[1]);
            split_tf32(Kt[16*wm + lr    ][k0 + lc + 4], ah[2], al[2]);
            split_tf32(Kt[16*wm + lr + 8][k0 + lc + 4], ah[3], al[3]);
#pragma unroll
            for (int ni = 0; ni < 4; ni++) {
                uint32_t bh0, bl0, bh1, bl1;
                split_tf32(Qt[32*wn + 8*ni + lr][k0 + lc],     bh0, bl0);
                split_tf32(Qt[32*wn + 8*ni + lr][k0 + lc + 4], bh1, bl1);
                // hi*hi
                asm volatile(
                    "mma.sync.aligned.m16n8k8.row.col.f32.tf32.tf32.f32 "
                    "{%0,%1,%2,%3}, {%4,%5,%6,%7}, {%8,%9}, {%0,%1,%2,%3};"
                    : "+f"(acc[ni][0]), "+f"(acc[ni][1]),
                      "+f"(acc[ni][2]), "+f"(acc[ni][3])
                    : "r"(ah[0]), "r"(ah[1]), "r"(ah[2]), "r"(ah[3]),
                      "r"(bh0), "r"(bh1));
                // hi*lo
                asm volatile(
                    "mma.sync.aligned.m16n8k8.row.col.f32.tf32.tf32.f32 "
                    "{%0,%1,%2,%3}, {%4,%5,%6,%7}, {%8,%9}, {%0,%1,%2,%3};"
                    : "+f"(acc[ni][0]), "+f"(acc[ni][1]),
                      "+f"(acc[ni][2]), "+f"(acc[ni][3])
                    : "r"(ah[0]), "r"(ah[1]), "r"(ah[2]), "r"(ah[3]),
                      "r"(bl0), "r"(bl1));
                // lo*hi
                asm volatile(
                    "mma.sync.aligned.m16n8k8.row.col.f32.tf32.tf32.f32 "
                    "{%0,%1,%2,%3}, {%4,%5,%6,%7}, {%8,%9}, {%0,%1,%2,%3};"
                    : "+f"(acc[ni][0]), "+f"(acc[ni][1]),
                      "+f"(acc[ni][2]), "+f"(acc[ni][3])
                    : "r"(al[0]), "r"(al[1]), "r"(al[2]), "r"(al[3]),
                      "r"(bh0), "r"(bh1));
            }
        }
#pragma unroll
        for (int ni = 0; ni < 4; ni++) {
            s0 += ex2(acc[ni][0]) + ex2(acc[ni][1]);
            s1 += ex2(acc[ni][2]) + ex2(acc[ni][3]);
        }
    }

    red[16*wm + lr    ][wn*4 + lc] = s0;
    __syncthreads();   // two writes to same array region from same thread set
    red[16*wm + lr + 8][wn*4 + lc] += 0.f;  // no-op keep ordering simple
    red[16*wm + lr + 8][wn*4 + lc] = s1;
    __syncthreads();
    if (t < 64) {
        float s = 0.f;
#pragma unroll
        for (int q = 0; q < 8; q++) s += red[t][q];
        g_psm[((size_t)b*NSPLIT + z)*NN + m0 + t] = s;
    }
}

// =====================================================================
// Reduce: combine NSPLIT partial sums -> inverse. grid (NN/256, B).
// =====================================================================
__global__ __launch_bounds__(256)
void attn_reduce_kernel()
{
    const int b = blockIdx.y;
    const int m = blockIdx.x * 256 + threadIdx.x;
    float s = 0.f;
#pragma unroll
    for (int z = 0; z < NSPLIT; z++)
        s += g_psm[((size_t)b*NSPLIT + z)*NN + m];
    g_sm[(size_t)b*NN + m] = 1.0f / s;
}

// =====================================================================
// Write pass: exact scalar-fp32 energy (log2 domain) + ex2 + normalize,
// single write of fp32 at_map + bf16 sidecar (both NORMALIZED).
// grid (NN/64 m-tiles, NSPLIT, B), block 256.
// =====================================================================
__global__ __launch_bounds__(256)
void attn_write_kernel(float* __restrict__ amap)
{
    __shared__ float Ks[CQK][64];
    __shared__ float Qs[CQK][64];

    const int b  = blockIdx.z;
    const int z  = blockIdx.y;
    const int m0 = blockIdx.x * 64;
    const int t  = threadIdx.x;
    const int tx = t & 15;
    const int ty = t >> 4;

    const float* qb = g_q + (size_t)b*CQK*NN;
    const float* kb = g_k + (size_t)b*CQK*NN;

    for (int idx = t; idx < CQK*64; idx += 256) {
        int c = idx >> 6, j = idx & 63;
        Ks[c][j] = kb[(size_t)c*NN + m0 + j];
    }

    float inv[4];
#pragma unroll
    for (int j = 0; j < 4; j++)
        inv[j] = g_sm[(size_t)b*NN + m0 + ty*4 + j];

    for (int nb = 0; nb < NN/(64*NSPLIT); nb++) {
        const int n0 = z*(NN/NSPLIT) + nb * 64;
        __syncthreads();
        for (int idx = t; idx < CQK*64; idx += 256) {
            int c = idx >> 6, j = idx & 63;
            Qs[c][j] = qb[(size_t)c*NN + n0 + j];
        }
        __syncthreads();

        unsigned long long e[4][2];
#pragma unroll
        for (int j = 0; j < 4; j++) { e[j][0] = 0ull; e[j][1] = 0ull; }

#pragma unroll
        for (int c = 0; c < CQK; c++) {
            unsigned long long q01 = *reinterpret_cast<const unsigned long long*>(&Qs[c][tx*4]);
            unsigned long long q23 = *reinterpret_cast<const unsigned long long*>(&Qs[c][tx*4+2]);
            float4 kv = *reinterpret_cast<const float4*>(&Ks[c][ty*4]);
            unsigned long long k0 = f2u_dup(kv.x), k1 = f2u_dup(kv.y),
                               k2 = f2u_dup(kv.z), k3 = f2u_dup(kv.w);
            e[0][0] = fma2(k0, q01, e[0][0]);  e[0][1] = fma2(k0, q23, e[0][1]);
            e[1][0] = fma2(k1, q01, e[1][0]);  e[1][1] = fma2(k1, q23, e[1][1]);
            e[2][0] = fma2(k2, q01, e[2][0]);  e[2][1] = fma2(k2, q23, e[2][1]);
            e[3][0] = fma2(k3, q01, e[3][0]);  e[3][1] = fma2(k3, q23, e[3][1]);
        }

#pragma unroll
        for (int j = 0; j < 4; j++) {
            float2 a  = u2f(e[j][0]);
            float2 c2 = u2f(e[j][1]);
            float4 o;
            o.x = ex2(a.x)  * inv[j];
            o.y = ex2(a.y)  * inv[j];
            o.z = ex2(c2.x) * inv[j];
            o.w = ex2(c2.y) * inv[j];
            const size_t row = (size_t)b*NN + (size_t)(m0 + ty*4 + j);
            *reinterpret_cast<float4*>(&amap[row*NN + n0 + tx*4]) = o;
            __nv_bfloat162 h0, h1;
            h0.x = __float2bfloat16_rn(o.x);  h0.y = __float2bfloat16_rn(o.y);
            h1.x = __float2bfloat16_rn(o.z);  h1.y = __float2bfloat16_rn(o.w);
            uint2 packed;
            packed.x = *reinterpret_cast<uint32_t*>(&h0);
            packed.y = *reinterpret_cast<uint32_t*>(&h1);
            *reinterpret_cast<uint2*>(&g_ah[row*NN + n0 + tx*4]) = packed;
        }
    }
}

// =====================================================================
// Kernel 4: SA GEMM via bf16 m16n8k16 + ldmatrix. Reads NORMALIZED
// bf16 attn map; epilogue applies gamma only.
// =====================================================================
#define HST 40
#define HSTAGE (128*HST)
#define HSTAGE_B (HSTAGE*2)            // 10240 bytes
#define SAH_SMEM_BYTES (4*HSTAGE_B)    // 40960 bytes

__device__ __forceinline__ void sah_load(uint32_t sbase, int s,
                                         const __nv_bfloat16* Vbh,
                                         const __nv_bfloat16* Abh,
                                         int n0, int t)
{
    const uint32_t voff = sbase + (uint32_t)(s*HSTAGE_B);
    const uint32_t aoff = sbase + (uint32_t)((2 + s)*HSTAGE_B);
#pragma unroll
    for (int it = 0; it < 2; it++) {
        int u = t + it*256;
        int row = u >> 2, q = u & 3;
        uint32_t so = (uint32_t)(row*80 + q*16);
        cp16(voff + so, Vbh + (size_t)row*NN + n0 + q*8);
        cp16(aoff + so, Abh + (size_t)row*NN + n0 + q*8);
    }
}

__global__ __launch_bounds__(256, 2)
void sa_gemm_bf16_kernel(const float* __restrict__ x,
                         const float* __restrict__ gamma,
                         float* __restrict__ dout)
{
    extern __shared__ __nv_bfloat16 hsm[];
    const uint32_t sbase = smem_u32(hsm);

    const int t    = threadIdx.x;
    const int w    = t >> 5;
    const int lane = t & 31;
    const int lr   = lane >> 2;
    const int lc   = lane & 3;
    const int wm   = w >> 2;
    const int wn   = w & 3;

    const int b  = blockIdx.z;
    const int c0 = blockIdx.y * 128;
    const int m0 = blockIdx.x * 128;

    const __nv_bfloat16* Vbh = g_vh + (size_t)b*CC*NN + (size_t)c0*NN;
    const __nv_bfloat16* Abh = g_ah + (size_t)b*NN*NN + (size_t)m0*NN;

    float acc[4][4][4];
#pragma unroll
    for (int mi = 0; mi < 4; mi++)
#pragma unroll
        for (int ni = 0; ni < 4; ni++)
#pragma unroll
            for (int r = 0; r < 4; r++) acc[mi][ni][r] = 0.f;

    sah_load(sbase, 0, Vbh, Abh, 0, t);
    asm volatile("cp.async.commit_group;" ::: "memory");

    const int NCH = NN/32;   // 128
    for (int i = 0; i < NCH; i++) {
        if (i + 1 < NCH) {
            sah_load(sbase, (i+1)&1, Vbh, Abh, (i+1)*32, t);
            asm volatile("cp.async.commit_group;" ::: "memory");
            asm volatile("cp.async.wait_group 1;" ::: "memory");
        } else {
            asm volatile("cp.async.wait_group 0;" ::: "memory");
        }
        __syncthreads();

        const uint32_t vst = sbase + (uint32_t)((i&1)*HSTAGE_B);
        const uint32_t ast = sbase + (uint32_t)((2 + (i&1))*HSTAGE_B);

#pragma unroll
        for (int ks = 0; ks < 2; ks++) {
            const int k0 = ks*16;
            uint32_t afr[4][4], bfr[4][2];
            const uint32_t colA = (uint32_t)((k0 + ((lane & 16) >> 1)) * 2);
#pragma unroll
            for (int mi = 0; mi < 4; mi++) {
                const uint32_t rowA = (uint32_t)(wm*64 + mi*16 + (lane & 15));
                const uint32_t addr = vst + rowA*80 + colA;
                asm volatile(
                    "ldmatrix.sync.aligned.m8n8.x4.shared.b16 {%0,%1,%2,%3}, [%4];"
                    : "=r"(afr[mi][0]), "=r"(afr[mi][1]),
                      "=r"(afr[mi][2]), "=r"(afr[mi][3])
                    : "r"(addr));
            }
            const uint32_t colB = (uint32_t)((k0 + (lane & 8)) * 2);
#pragma unroll
            for (int nb = 0; nb < 2; nb++) {
                const uint32_t rowB = (uint32_t)(wn*32 + nb*16 + (lane & 7) + ((lane & 16) >> 1));
                const uint32_t addr = ast + rowB*80 + colB;
                uint32_t r0, r1, r2, r3;
                asm volatile(
                    "ldmatrix.sync.aligned.m8n8.x4.shared.b16 {%0,%1,%2,%3}, [%4];"
                    : "=r"(r0), "=r"(r1), "=r"(r2), "=r"(r3)
                    : "r"(addr));
                bfr[nb*2    ][0] = r0;  bfr[nb*2    ][1] = r1;
                bfr[nb*2 + 1][0] = r2;  bfr[nb*2 + 1][1] = r3;
            }
#pragma unroll
            for (int mi = 0; mi < 4; mi++)
#pragma unroll
                for (int ni = 0; ni < 4; ni++) {
                    asm volatile(
                        "mma.sync.aligned.m16n8k16.row.col.f32.bf16.bf16.f32 "
                        "{%0,%1,%2,%3}, {%4,%5,%6,%7}, {%8,%9}, {%0,%1,%2,%3};"
                        : "+f"(acc[mi][ni][0]), "+f"(acc[mi][ni][1]),
                          "+f"(acc[mi][ni][2]), "+f"(acc[mi][ni][3])
                        : "r"(afr[mi][0]), "r"(afr[mi][1]),
                          "r"(afr[mi][2]), "r"(afr[mi][3]),
                          "r"(bfr[ni][0]), "r"(bfr[ni][1]));
                }
        }
        __syncthreads();
    }

    // epilogue: out = x + gamma * D   (map already normalized)
    const float g = __ldg(gamma);
#pragma unroll
    for (int mi = 0; mi < 4; mi++) {
        const int r0 = c0 + wm*64 + mi*16 + lr;
#pragma unroll
        for (int ni = 0; ni < 4; ni++) {
            const int cb = m0 + wn*32 + ni*8 + lc*2;
            size_t o1 = ((size_t)(b*CC + r0))*NN + cb;
            size_t o2 = ((size_t)(b*CC + r0 + 8))*NN + cb;
            float2 x1 = *reinterpret_cast<const float2*>(x + o1);
            float2 x2 = *reinterpret_cast<const float2*>(x + o2);
            float2 d1, d2;
            d1.x = x1.x + g*acc[mi][ni][0];
            d1.y = x1.y + g*acc[mi][ni][1];
            d2.x = x2.x + g*acc[mi][ni][2];
            d2.y = x2.y + g*acc[mi][ni][3];
            *reinterpret_cast<float2*>(dout + o1) = d1;
            *reinterpret_cast<float2*>(dout + o2) = d2;
        }
    }
}

// =====================================================================
// launcher: single stream
// =====================================================================
extern "C" void kernel_launch(void* const* d_in, const int* in_sizes, int n_in,
                              void* d_out, int out_size)
{
    const float* x     = (const float*)d_in[0];
    const float* wq    = (const float*)d_in[1];
    const float* bq    = (const float*)d_in[2];
    const float* wk    = (const float*)d_in[3];
    const float* bk    = (const float*)d_in[4];
    const float* wv    = (const float*)d_in[5];
    const float* bv    = (const float*)d_in[6];
    const float* gamma = (const float*)d_in[7];

    float* out  = (float*)d_out;
    float* amap = out + OUT_ELEMS;

    proj_qk_kernel<<<dim3(NN/256, BB, 2), 128>>>(x, wq, bq, wk, bk);
    proj_v_kernel <<<dim3(NN/256, 8, BB), 128>>>(x, wv, bv);
    attn_stats_tc_kernel<<<dim3(NN/64, NSPLIT, BB), 256>>>();
    attn_reduce_kernel<<<dim3(NN/256, BB), 256>>>();
    attn_write_kernel<<<dim3(NN/64, NSPLIT, BB), 256>>>(amap);
    sa_gemm_bf16_kernel<<<dim3(NN/128, CC/128, BB), 256, SAH_SMEM_BYTES>>>(x, gamma, out);
}

// round 17
// speedup vs baseline: 1.0642x; 1.0642x over previous
#include <cuda_runtime.h>
#include <cuda_bf16.h>
#include <cstdint>
#include <cstddef>

// Problem constants
#define BB   4
#define CC   256
#define CQK  32
#define NN   4096          // H*W = 64*64
#define OUT_ELEMS (BB*CC*NN)
#define NSPLIT 8           // n-dim split for exp pass

#define LOG2E 1.4426950408889634f

// ---------------- scratch (device globals: allocation-free) ----------------
__device__ __align__(128) float g_q[BB*CQK*NN];
__device__ __align__(128) float g_k[BB*CQK*NN];   // pre-scaled by log2(e)
__device__ __align__(128) __nv_bfloat16 g_vh[BB*CC*NN];      // V in bf16
__device__ __align__(128) __nv_bfloat16 g_ah[BB*NN*NN];      // UNNORMALIZED exp map, bf16
__device__ float g_sm[BB*NN];            // inv column sums
__device__ float g_psm[BB*NSPLIT*NN];    // partial column sums

// ---------------- f32x2 packed helpers ----------------
__device__ __forceinline__ unsigned long long f2u_dup(float x) {
    unsigned long long r;
    asm("mov.b64 %0, {%1, %1};" : "=l"(r) : "f"(x));
    return r;
}
__device__ __forceinline__ float2 u2f(unsigned long long v) {
    float2 r;
    asm("mov.b64 {%0, %1}, %2;" : "=f"(r.x), "=f"(r.y) : "l"(v));
    return r;
}
__device__ __forceinline__ unsigned long long fma2(unsigned long long a,
                                                   unsigned long long b,
                                                   unsigned long long c) {
    unsigned long long d;
    asm("fma.rn.f32x2 %0, %1, %2, %3;" : "=l"(d) : "l"(a), "l"(b), "l"(c));
    return d;
}
__device__ __forceinline__ float ex2(float x) {   // 2^x (K pre-scaled by log2e)
    float r;
    asm("ex2.approx.ftz.f32 %0, %1;" : "=f"(r) : "f"(x));
    return r;
}

// ---------------- smem / cp.async helpers ----------------
__device__ __forceinline__ uint32_t smem_u32(const void* p) {
    uint32_t a;
    asm("{ .reg .u64 t; cvta.to.shared.u64 t, %1; cvt.u32.u64 %0, t; }" : "=r"(a) : "l"(p));
    return a;
}
__device__ __forceinline__ void cp16(uint32_t dst, const void* src) {
    asm volatile("cp.async.cg.shared.global [%0], [%1], 16;" :: "r"(dst), "l"(src) : "memory");
}

// =====================================================================
// Kernel 1: q/k projection, f32x2 over output-channel pairs.
// K pre-multiplied by log2(e) so exp becomes bare ex2.
// grid (NN/256, B, 2[q|k]), block 128.
// =====================================================================
__global__ __launch_bounds__(128)
void proj_qk_kernel(const float* __restrict__ x,
                    const float* __restrict__ wq, const float* __restrict__ bq,
                    const float* __restrict__ wk, const float* __restrict__ bk)
{
    __shared__ float ws[256*40];
    __shared__ float bs[CQK];

    const int sel = blockIdx.z;
    const float* W  = sel ? wk : wq;
    const float* Bv = sel ? bk : bq;
    float* Out      = sel ? g_k : g_q;
    const float osc = sel ? LOG2E : 1.0f;

    const int t = threadIdx.x;
    for (int idx = t; idx < CQK*CC; idx += 128) {
        int o = idx >> 8;
        int c = idx & 255;
        ws[c*40 + o] = W[idx];
    }
    if (t < CQK) bs[t] = Bv[t];
    __syncthreads();

    const int b = blockIdx.y;
    const int n = blockIdx.x * 256 + t*2;

    unsigned long long acc2[2][16];
#pragma unroll
    for (int i = 0; i < 2; i++)
#pragma unroll
        for (int op = 0; op < 16; op++) acc2[i][op] = 0ull;

    const float* xp = x + (size_t)b*CC*NN + n;
#pragma unroll 2
    for (int c = 0; c < CC; c++) {
        float2 xv = *reinterpret_cast<const float2*>(xp + (size_t)c*NN);
        unsigned long long xd0 = f2u_dup(xv.x);
        unsigned long long xd1 = f2u_dup(xv.y);
        const float* wr = &ws[c*40];
#pragma unroll
        for (int op = 0; op < 16; op++) {
            unsigned long long w2 = *reinterpret_cast<const unsigned long long*>(&wr[op*2]);
            acc2[0][op] = fma2(w2, xd0, acc2[0][op]);
            acc2[1][op] = fma2(w2, xd1, acc2[1][op]);
        }
    }
    float* opt = Out + (size_t)b*CQK*NN + n;
#pragma unroll
    for (int op = 0; op < 16; op++) {
        float2 p0 = u2f(acc2[0][op]);
        float2 p1 = u2f(acc2[1][op]);
        float2 r0; r0.x = (p0.x + bs[2*op])*osc;     r0.y = (p1.x + bs[2*op])*osc;
        float2 r1; r1.x = (p0.y + bs[2*op + 1])*osc; r1.y = (p1.y + bs[2*op + 1])*osc;
        *reinterpret_cast<float2*>(opt + (size_t)(2*op)*NN)     = r0;
        *reinterpret_cast<float2*>(opt + (size_t)(2*op + 1)*NN) = r1;
    }
}

// =====================================================================
// Kernel 2: v projection -> bf16 (f32x2). grid (NN/256, 8, B), block 128.
// =====================================================================
__global__ __launch_bounds__(128)
void proj_v_kernel(const float* __restrict__ x,
                   const float* __restrict__ wv, const float* __restrict__ bv)
{
    __shared__ float ws[256*40];
    __shared__ float bs[32];

    const int t  = threadIdx.x;
    const int o0 = blockIdx.y * 32;

    for (int idx = t; idx < 32*CC; idx += 128) {
        int o = idx >> 8;
        int c = idx & 255;
        ws[c*40 + o] = wv[(size_t)(o0 + o)*CC + c];
    }
    if (t < 32) bs[t] = bv[o0 + t];
    __syncthreads();

    const int b = blockIdx.z;
    const int n = blockIdx.x * 256 + t*2;

    unsigned long long acc2[2][16];
#pragma unroll
    for (int i = 0; i < 2; i++)
#pragma unroll
        for (int op = 0; op < 16; op++) acc2[i][op] = 0ull;

    const float* xp = x + (size_t)b*CC*NN + n;
#pragma unroll 2
    for (int c = 0; c < CC; c++) {
        float2 xv = *reinterpret_cast<const float2*>(xp + (size_t)c*NN);
        unsigned long long xd0 = f2u_dup(xv.x);
        unsigned long long xd1 = f2u_dup(xv.y);
        const float* wr = &ws[c*40];
#pragma unroll
        for (int op = 0; op < 16; op++) {
            unsigned long long w2 = *reinterpret_cast<const unsigned long long*>(&wr[op*2]);
            acc2[0][op] = fma2(w2, xd0, acc2[0][op]);
            acc2[1][op] = fma2(w2, xd1, acc2[1][op]);
        }
    }
    __nv_bfloat16* opt = g_vh + (size_t)b*CC*NN + (size_t)o0*NN + n;
#pragma unroll
    for (int op = 0; op < 16; op++) {
        float2 p0 = u2f(acc2[0][op]);
        float2 p1 = u2f(acc2[1][op]);
        __nv_bfloat162 h0, h1;
        h0.x = __float2bfloat16_rn(p0.x + bs[2*op]);
        h0.y = __float2bfloat16_rn(p1.x + bs[2*op]);
        h1.x = __float2bfloat16_rn(p0.y + bs[2*op + 1]);
        h1.y = __float2bfloat16_rn(p1.y + bs[2*op + 1]);
        *reinterpret_cast<__nv_bfloat162*>(opt + (size_t)(2*op)*NN)     = h0;
        *reinterpret_cast<__nv_bfloat162*>(opt + (size_t)(2*op + 1)*NN) = h1;
    }
}

// =====================================================================
// Exp pass: energy (log2 domain) + ex2, writes unnormalized fp32 amap
// + bf16 sidecar, accumulates column sums. Q staged via cp.async
// double-buffer (prefetch chunk i+1 during compute of chunk i).
// grid (NN/64 m-tiles, NSPLIT, B), block 256.
// =====================================================================
__global__ __launch_bounds__(256)
void attn_exp_kernel(float* __restrict__ amap)
{
    __shared__ float Ks[CQK][64];
    __shared__ float Qs[2][CQK][64];
    __shared__ float reds[64][17];

    const int b  = blockIdx.z;
    const int z  = blockIdx.y;
    const int m0 = blockIdx.x * 64;
    const int t  = threadIdx.x;
    const int tx = t & 15;
    const int ty = t >> 4;

    const float* qb = g_q + (size_t)b*CQK*NN;
    const float* kb = g_k + (size_t)b*CQK*NN;
    const uint32_t qs_base = smem_u32(&Qs[0][0][0]);

    for (int idx = t; idx < CQK*64; idx += 256) {
        int c = idx >> 6, j = idx & 63;
        Ks[c][j] = kb[(size_t)c*NN + m0 + j];
    }

    // async Q chunk loader: 512 cp16 per chunk, 2 per thread
    auto load_q = [&](int buf, int n0) {
#pragma unroll
        for (int k = 0; k < 2; k++) {
            int u = t + k*256;          // 0..511
            int c = u >> 4;             // 0..31
            int seg = u & 15;           // 0..15 (x4 floats)
            cp16(qs_base + (uint32_t)((buf*CQK*64 + c*64 + seg*4)*4),
                 qb + (size_t)c*NN + n0 + seg*4);
        }
    };

    const int NCHK = NN/(64*NSPLIT);    // 8
    const int nbase = z*(NN/NSPLIT);

    load_q(0, nbase);
    asm volatile("cp.async.commit_group;" ::: "memory");

    float runsum[4];
#pragma unroll
    for (int j = 0; j < 4; j++) runsum[j] = 0.f;

    for (int nb = 0; nb < NCHK; nb++) {
        const int n0 = nbase + nb * 64;
        if (nb + 1 < NCHK) {
            load_q((nb+1)&1, nbase + (nb+1)*64);
            asm volatile("cp.async.commit_group;" ::: "memory");
            asm volatile("cp.async.wait_group 1;" ::: "memory");
        } else {
            asm volatile("cp.async.wait_group 0;" ::: "memory");
        }
        __syncthreads();

        const float (*Q)[64] = Qs[nb&1];

        unsigned long long e[4][2];
#pragma unroll
        for (int j = 0; j < 4; j++) { e[j][0] = 0ull; e[j][1] = 0ull; }

#pragma unroll
        for (int c = 0; c < CQK; c++) {
            unsigned long long q01 = *reinterpret_cast<const unsigned long long*>(&Q[c][tx*4]);
            unsigned long long q23 = *reinterpret_cast<const unsigned long long*>(&Q[c][tx*4+2]);
            float4 kv = *reinterpret_cast<const float4*>(&Ks[c][ty*4]);
            unsigned long long k0 = f2u_dup(kv.x), k1 = f2u_dup(kv.y),
                               k2 = f2u_dup(kv.z), k3 = f2u_dup(kv.w);
            e[0][0] = fma2(k0, q01, e[0][0]);  e[0][1] = fma2(k0, q23, e[0][1]);
            e[1][0] = fma2(k1, q01, e[1][0]);  e[1][1] = fma2(k1, q23, e[1][1]);
            e[2][0] = fma2(k2, q01, e[2][0]);  e[2][1] = fma2(k2, q23, e[2][1]);
            e[3][0] = fma2(k3, q01, e[3][0]);  e[3][1] = fma2(k3, q23, e[3][1]);
        }

#pragma unroll
        for (int j = 0; j < 4; j++) {
            float2 a  = u2f(e[j][0]);
            float2 c2 = u2f(e[j][1]);
            float4 o;
            o.x = ex2(a.x);
            o.y = ex2(a.y);
            o.z = ex2(c2.x);
            o.w = ex2(c2.y);
            runsum[j] += (o.x + o.y) + (o.z + o.w);
            const size_t row = (size_t)b*NN + (size_t)(m0 + ty*4 + j);
            *reinterpret_cast<float4*>(&amap[row*NN + n0 + tx*4]) = o;
            __nv_bfloat162 h0, h1;
            h0.x = __float2bfloat16_rn(o.x);  h0.y = __float2bfloat16_rn(o.y);
            h1.x = __float2bfloat16_rn(o.z);  h1.y = __float2bfloat16_rn(o.w);
            uint2 packed;
            packed.x = *reinterpret_cast<uint32_t*>(&h0);
            packed.y = *reinterpret_cast<uint32_t*>(&h1);
            *reinterpret_cast<uint2*>(&g_ah[row*NN + n0 + tx*4]) = packed;
        }
        __syncthreads();
    }

#pragma unroll
    for (int j = 0; j < 4; j++) reds[ty*4 + j][tx] = runsum[j];
    __syncthreads();
    if (t < 64) {
        float s = 0.f;
#pragma unroll
        for (int q = 0; q < 16; q++) s += reds[t][q];
        g_psm[((size_t)b*NSPLIT + z)*NN + m0 + t] = s;
    }
}

// =====================================================================
// Reduce: combine NSPLIT partial sums -> inverse. grid (NN/256, B).
// =====================================================================
__global__ __launch_bounds__(256)
void attn_reduce_kernel()
{
    const int b = blockIdx.y;
    const int m = blockIdx.x * 256 + threadIdx.x;
    float s = 0.f;
#pragma unroll
    for (int z = 0; z < NSPLIT; z++)
        s += g_psm[((size_t)b*NSPLIT + z)*NN + m];
    g_sm[(size_t)b*NN + m] = 1.0f / s;
}

// =====================================================================
// Normalize fp32 at_map rows in place. One block per row; each thread
// handles 4 INDEPENDENT float4s (MLP=4) for latency cover.
// grid (NN, B), block 256.
// =====================================================================
__global__ __launch_bounds__(256)
void attn_norm_kernel(float* __restrict__ amap)
{
    const int b = blockIdx.y;
    const int m = blockIdx.x;
    const float inv = g_sm[(size_t)b*NN + m];
    float4* row = reinterpret_cast<float4*>(amap + ((size_t)(b*NN + m))*NN);
    const int i = threadIdx.x;
    float4 v0 = row[i];
    float4 v1 = row[i + 256];
    float4 v2 = row[i + 512];
    float4 v3 = row[i + 768];
    v0.x *= inv; v0.y *= inv; v0.z *= inv; v0.w *= inv;
    v1.x *= inv; v1.y *= inv; v1.z *= inv; v1.w *= inv;
    v2.x *= inv; v2.y *= inv; v2.z *= inv; v2.w *= inv;
    v3.x *= inv; v3.y *= inv; v3.z *= inv; v3.w *= inv;
    row[i]       = v0;
    row[i + 256] = v1;
    row[i + 512] = v2;
    row[i + 768] = v3;
}

// =====================================================================
// Kernel 4: SA GEMM via bf16 m16n8k16 + ldmatrix. Reads UNNORMALIZED
// bf16 exp map; epilogue applies gamma * inv_s[m].
// CTA 128(c)x128(m), BK=32, THREE-stage cp.async pipeline.
// =====================================================================
#define HST 40
#define HSTAGE (128*HST)
#define HSTAGE_B (HSTAGE*2)                 // 10240 bytes
#define SAH_STAGES 3
#define SAH_SMEM_BYTES (2*SAH_STAGES*HSTAGE_B)   // 61440 bytes

__device__ __forceinline__ void sah_load(uint32_t sbase, int s,
                                         const __nv_bfloat16* Vbh,
                                         const __nv_bfloat16* Abh,
                                         int n0, int t)
{
    const uint32_t voff = sbase + (uint32_t)(s*HSTAGE_B);
    const uint32_t aoff = sbase + (uint32_t)((SAH_STAGES + s)*HSTAGE_B);
#pragma unroll
    for (int it = 0; it < 2; it++) {
        int u = t + it*256;
        int row = u >> 2, q = u & 3;
        uint32_t so = (uint32_t)(row*80 + q*16);
        cp16(voff + so, Vbh + (size_t)row*NN + n0 + q*8);
        cp16(aoff + so, Abh + (size_t)row*NN + n0 + q*8);
    }
}

__global__ __launch_bounds__(256, 2)
void sa_gemm_bf16_kernel(const float* __restrict__ x,
                         const float* __restrict__ gamma,
                         float* __restrict__ dout)
{
    extern __shared__ __nv_bfloat16 hsm[];
    __shared__ float sInv[128];
    const uint32_t sbase = smem_u32(hsm);

    const int t    = threadIdx.x;
    const int w    = t >> 5;
    const int lane = t & 31;
    const int lr   = lane >> 2;
    const int lc   = lane & 3;
    const int wm   = w >> 2;
    const int wn   = w & 3;

    const int b  = blockIdx.z;
    const int c0 = blockIdx.y * 128;
    const int m0 = blockIdx.x * 128;

    const __nv_bfloat16* Vbh = g_vh + (size_t)b*CC*NN + (size_t)c0*NN;
    const __nv_bfloat16* Abh = g_ah + (size_t)b*NN*NN + (size_t)m0*NN;

    if (t < 128) sInv[t] = g_sm[(size_t)b*NN + m0 + t];

    float acc[4][4][4];
#pragma unroll
    for (int mi = 0; mi < 4; mi++)
#pragma unroll
        for (int ni = 0; ni < 4; ni++)
#pragma unroll
            for (int r = 0; r < 4; r++) acc[mi][ni][r] = 0.f;

    sah_load(sbase, 0, Vbh, Abh, 0, t);
    asm volatile("cp.async.commit_group;" ::: "memory");
    sah_load(sbase, 1, Vbh, Abh, 32, t);
    asm volatile("cp.async.commit_group;" ::: "memory");

    const int NCH = NN/32;   // 128
    for (int i = 0; i < NCH; i++) {
        if (i + 2 < NCH) {
            sah_load(sbase, (i+2)%SAH_STAGES, Vbh, Abh, (i+2)*32, t);
            asm volatile("cp.async.commit_group;" ::: "memory");
            asm volatile("cp.async.wait_group 2;" ::: "memory");
        } else if (i + 1 < NCH) {
            asm volatile("cp.async.wait_group 1;" ::: "memory");
        } else {
            asm volatile("cp.async.wait_group 0;" ::: "memory");
        }
        __syncthreads();

        const int cs = i % SAH_STAGES;
        const uint32_t vst = sbase + (uint32_t)(cs*HSTAGE_B);
        const uint32_t ast = sbase + (uint32_t)((SAH_STAGES + cs)*HSTAGE_B);

#pragma unroll
        for (int ks = 0; ks < 2; ks++) {
            const int k0 = ks*16;
            uint32_t afr[4][4], bfr[4][2];
            const uint32_t colA = (uint32_t)((k0 + ((lane & 16) >> 1)) * 2);
#pragma unroll
            for (int mi = 0; mi < 4; mi++) {
                const uint32_t rowA = (uint32_t)(wm*64 + mi*16 + (lane & 15));
                const uint32_t addr = vst + rowA*80 + colA;
                asm volatile(
                    "ldmatrix.sync.aligned.m8n8.x4.shared.b16 {%0,%1,%2,%3}, [%4];"
                    : "=r"(afr[mi][0]), "=r"(afr[mi][1]),
                      "=r"(afr[mi][2]), "=r"(afr[mi][3])
                    : "r"(addr));
            }
            const uint32_t colB = (uint32_t)((k0 + (lane & 8)) * 2);
#pragma unroll
            for (int nb = 0; nb < 2; nb++) {
                const uint32_t rowB = (uint32_t)(wn*32 + nb*16 + (lane & 7) + ((lane & 16) >> 1));
                const uint32_t addr = ast + rowB*80 + colB;
                uint32_t r0, r1, r2, r3;
                asm volatile(
                    "ldmatrix.sync.aligned.m8n8.x4.shared.b16 {%0,%1,%2,%3}, [%4];"
                    : "=r"(r0), "=r"(r1), "=r"(r2), "=r"(r3)
                    : "r"(addr));
                bfr[nb*2    ][0] = r0;  bfr[nb*2    ][1] = r1;
                bfr[nb*2 + 1][0] = r2;  bfr[nb*2 + 1][1] = r3;
            }
#pragma unroll
            for (int mi = 0; mi < 4; mi++)
#pragma unroll
                for (int ni = 0; ni < 4; ni++) {
                    asm volatile(
                        "mma.sync.aligned.m16n8k16.row.col.f32.bf16.bf16.f32 "
                        "{%0,%1,%2,%3}, {%4,%5,%6,%7}, {%8,%9}, {%0,%1,%2,%3};"
                        : "+f"(acc[mi][ni][0]), "+f"(acc[mi][ni][1]),
                          "+f"(acc[mi][ni][2]), "+f"(acc[mi][ni][3])
                        : "r"(afr[mi][0]), "r"(afr[mi][1]),
                          "r"(afr[mi][2]), "r"(afr[mi][3]),
                          "r"(bfr[ni][0]), "r"(bfr[ni][1]));
                }
        }
        __syncthreads();
    }

    // epilogue: out = x + gamma * inv_s[m] * D
    const float g = __ldg(gamma);
#pragma unroll
    for (int mi = 0; mi < 4; mi++) {
        const int r0 = c0 + wm*64 + mi*16 + lr;
#pragma unroll
        for (int ni = 0; ni < 4; ni++) {
            const int cb = wn*32 + ni*8 + lc*2;
            const float s0 = g * sInv[cb];
            const float s1 = g * sInv[cb + 1];
            size_t o1 = ((size_t)(b*CC + r0))*NN + m0 + cb;
            size_t o2 = ((size_t)(b*CC + r0 + 8))*NN + m0 + cb;
            float2 x1 = *reinterpret_cast<const float2*>(x + o1);
            float2 x2 = *reinterpret_cast<const float2*>(x + o2);
            float2 d1, d2;
            d1.x = x1.x + s0*acc[mi][ni][0];
            d1.y = x1.y + s1*acc[mi][ni][1];
            d2.x = x2.x + s0*acc[mi][ni][2];
            d2.y = x2.y + s1*acc[mi][ni][3];
            *reinterpret_cast<float2*>(dout + o1) = d1;
            *reinterpret_cast<float2*>(dout + o2) = d2;
        }
    }
}

// =====================================================================
// launcher: single stream
// =====================================================================
extern "C" void kernel_launch(void* const* d_in, const int* in_sizes, int n_in,
                              void* d_out, int out_size)
{
    const float* x     = (const float*)d_in[0];
    const float* wq    = (const float*)d_in[1];
    const float* bq    = (const float*)d_in[2];
    const float* wk    = (const float*)d_in[3];
    const float* bk    = (const float*)d_in[4];
    const float* wv    = (const float*)d_in[5];
    const float* bv    = (const float*)d_in[6];
    const float* gamma = (const float*)d_in[7];

    float* out  = (float*)d_out;
    float* amap = out + OUT_ELEMS;

    // >48KB dynamic smem needs opt-in; host-side attribute set is
    // idempotent and capture-safe (no stream work enqueued).
    cudaFuncSetAttribute(sa_gemm_bf16_kernel,
                         cudaFuncAttributeMaxDynamicSharedMemorySize, SAH_SMEM_BYTES);

    proj_qk_kernel<<<dim3(NN/256, BB, 2), 128>>>(x, wq, bq, wk, bk);
    proj_v_kernel <<<dim3(NN/256, 8, BB), 128>>>(x, wv, bv);
    attn_exp_kernel<<<dim3(NN/64, NSPLIT, BB), 256>>>(amap);
    attn_reduce_kernel<<<dim3(NN/256, BB), 256>>>();
    attn_norm_kernel<<<dim3(NN, BB), 256>>>(amap);
    sa_gemm_bf16_kernel<<<dim3(NN/128, CC/128, BB), 256, SAH_SMEM_BYTES>>>(x, gamma, out);
}